// round 16
// baseline (speedup 1.0000x reference)
#include <cuda_runtime.h>
#include <cuda_fp16.h>
#include <cstdint>

// Problem constants (fixed shapes)
#define BATCH 4
#define CH    256
#define HH    64
#define WW    64
#define HWSZ  4096
#define KKN   9
#define DGN   4
#define KDIM  2304          // KKN*CH (GEMM K), ordered k' = kk*256 + c
#define NDIM  16384         // BATCH*HWSZ (GEMM N)
#define GROUPS 32
#define GRP_ELEMS 32768

// ---- scratch (device globals; allocation-free) ----
__device__ __align__(16) __half g_wt[CH * KDIM];   // [o][k'], k' = kk*256 + c
__device__ float g_sum[BATCH * GROUPS];
__device__ float g_sqs[BATCH * GROUPS];

// ---------------------------------------------------------------------------
// PTX helpers — family-agnostic only (compute_103 target: no tcgen05/TMA)
// ---------------------------------------------------------------------------
__device__ __forceinline__ uint32_t smem_u32(const void* p) {
    uint32_t a;
    asm("{ .reg .u64 t; cvta.to.shared.u64 t, %1; cvt.u32.u64 %0, t; }" : "=r"(a) : "l"(p));
    return a;
}
__device__ __forceinline__ void cp16(uint32_t dst, const void* src) {
    asm volatile("cp.async.cg.shared.global [%0], [%1], 16;" :: "r"(dst), "l"(src) : "memory");
}
#define CP_COMMIT() asm volatile("cp.async.commit_group;" ::: "memory")
#define CP_WAIT0()  asm volatile("cp.async.wait_group 0;" ::: "memory")

#define LDSM_X4(r, addr) \
    asm volatile("ldmatrix.sync.aligned.m8n8.x4.shared.b16 {%0,%1,%2,%3}, [%4];" \
        : "=r"((r)[0]), "=r"((r)[1]), "=r"((r)[2]), "=r"((r)[3]) : "r"(addr))
#define LDSM_X4T(r0, r1, r2, r3, addr) \
    asm volatile("ldmatrix.sync.aligned.m8n8.x4.trans.shared.b16 {%0,%1,%2,%3}, [%4];" \
        : "=r"(r0), "=r"(r1), "=r"(r2), "=r"(r3) : "r"(addr))

#define MMA(d, a, b) \
    asm volatile("mma.sync.aligned.m16n8k16.row.col.f32.f16.f16.f32 " \
        "{%0,%1,%2,%3}, {%4,%5,%6,%7}, {%8,%9}, {%0,%1,%2,%3};" \
        : "+f"((d)[0]), "+f"((d)[1]), "+f"((d)[2]), "+f"((d)[3]) \
        : "r"((a)[0]), "r"((a)[1]), "r"((a)[2]), "r"((a)[3]), "r"((b)[0]), "r"((b)[1]))

// ---------------------------------------------------------------------------
// 1) Weight repack to fp16, k' = kk*256 + c ordering; zero GN accumulators
//    g_wt[o*2304 + kk*256 + c] = wd[(o*256 + c)*9 + kk]
// ---------------------------------------------------------------------------
__global__ void repack_kernel(const float* __restrict__ wd) {
    int d = blockIdx.x * 256 + threadIdx.x;   // < 589824
    int o  = d / KDIM;
    int r  = d - o * KDIM;
    int kk = r >> 8;
    int c  = r & 255;
    g_wt[d] = __float2half_rn(wd[(o * CH + c) * KKN + kk]);
    if (blockIdx.x == 0 && threadIdx.x < BATCH * GROUPS) {
        g_sum[threadIdx.x] = 0.0f;
        g_sqs[threadIdx.x] = 0.0f;
    }
}

// ---------------------------------------------------------------------------
// 2) FUSED deformable-im2col + fp16 HMMA GEMM + GN partial stats.
//    CTA: M=256 (all o) x N=64 (hw). grid = 256 CTAs (b*64 + hw-tile).
//    K-chunk 64 = chunk ch -> (kk = ch>>2, dg = ch&3); 2-stage smem pipeline.
//    Producer: gather/interp B tile on the fly (col never hits DRAM).
// ---------------------------------------------------------------------------
#define NCHUNK  36
#define ST_B    32768               // A: 256 rows * 128B (XOR swizzle); B: 64 rows * 128B
#define STAGE   40960
#define GEMM_SMEM (2 * STAGE)       // 81920 -> 2 CTAs/SM

__global__ __launch_bounds__(256, 2)
void fused_gemm_kernel(float* __restrict__ out,
                       const float* __restrict__ x,
                       const float* __restrict__ shp,
                       const float* __restrict__ w_off) {
    extern __shared__ __align__(128) char smem[];
    const uint32_t sb = smem_u32(smem);
    const int tid  = threadIdx.x;
    const int lane = tid & 31;
    const int wid  = tid >> 5;
    const int b    = blockIdx.x >> 6;
    const int hwB  = (blockIdx.x & 63) * 64;

    float acc[2][8][4];
    #pragma unroll
    for (int mt = 0; mt < 2; mt++)
        #pragma unroll
        for (int nt = 0; nt < 8; nt++)
            #pragma unroll
            for (int q = 0; q < 4; q++) acc[mt][nt][q] = 0.0f;

    // ldmatrix lane geometry
    const int arow = (lane & 7) + ((lane >> 3) & 1) * 8;
    const int asel = lane >> 4;
    const int bk   = lane & 15;
    const int bsel = lane >> 4;

    // ---- producer: fill stage s with chunk ch ----
    #define PRODUCE(ch_, stg_)                                                    \
    do {                                                                          \
        const int kk_ = (ch_) >> 2, dg_ = (ch_) & 3;                              \
        /* A slab: g_wt[o][ch*64 + g*8], 2048 x 16B, XOR-swizzled rows */         \
        _Pragma("unroll")                                                         \
        for (int p_ = 0; p_ < 8; p_++) {                                          \
            int i_ = tid + p_ * 256;                                              \
            int o_ = i_ >> 3, gg_ = i_ & 7;                                       \
            cp16((stg_) + o_ * 128 + ((gg_ ^ (o_ & 7)) << 4),                     \
                 g_wt + (size_t)o_ * KDIM + (ch_) * 64 + gg_ * 8);                \
        }                                                                         \
        CP_COMMIT();                                                              \
        /* B tile: 64 k-rows x 64 n, each thread: fixed n-pair, 8 k-rows */       \
        const int np_ = tid & 31;                                                 \
        float W_[2][4]; int I_[2][4];                                             \
        _Pragma("unroll")                                                         \
        for (int u_ = 0; u_ < 2; u_++) {                                          \
            int hw_ = hwB + np_ * 2 + u_;                                         \
            int h_ = hw_ >> 6, w_ = hw_ & 63;                                     \
            float s0_ = shp[((b * 4 + 0) << 12) + hw_];                           \
            float s1_ = shp[((b * 4 + 1) << 12) + hw_];                           \
            float s2_ = shp[((b * 4 + 2) << 12) + hw_];                           \
            float s3_ = shp[((b * 4 + 3) << 12) + hw_];                           \
            const float* wo_ = w_off + (dg_ * 18 + kk_ * 2) * 4;                  \
            float dy_ = __ldg(wo_+0)*s0_ + __ldg(wo_+1)*s1_                       \
                      + __ldg(wo_+2)*s2_ + __ldg(wo_+3)*s3_;                      \
            float dx_ = __ldg(wo_+4)*s0_ + __ldg(wo_+5)*s1_                       \
                      + __ldg(wo_+6)*s2_ + __ldg(wo_+7)*s3_;                      \
            float yf_ = (float)(h_ - 1 + kk_ / 3) + dy_;                          \
            float xf_ = (float)(w_ - 1 + kk_ % 3) + dx_;                          \
            float y0f_ = floorf(yf_), x0f_ = floorf(xf_);                         \
            float wy1_ = yf_ - y0f_, wx1_ = xf_ - x0f_;                           \
            float wy0_ = 1.0f - wy1_, wx0_ = 1.0f - wx1_;                         \
            int y0_ = (int)y0f_, x0_ = (int)x0f_;                                 \
            int y1_ = y0_ + 1,   x1_ = x0_ + 1;                                   \
            bool vy0_ = (y0_ >= 0) & (y0_ < HH);                                  \
            bool vy1_ = (y1_ >= 0) & (y1_ < HH);                                  \
            bool vx0_ = (x0_ >= 0) & (x0_ < WW);                                  \
            bool vx1_ = (x1_ >= 0) & (x1_ < WW);                                  \
            int y0c_ = min(max(y0_, 0), HH-1), y1c_ = min(max(y1_, 0), HH-1);     \
            int x0c_ = min(max(x0_, 0), WW-1), x1c_ = min(max(x1_, 0), WW-1);     \
            W_[u_][0] = wy0_ * wx0_ * (float)(vy0_ & vx0_);                       \
            W_[u_][1] = wy0_ * wx1_ * (float)(vy0_ & vx1_);                       \
            W_[u_][2] = wy1_ * wx0_ * (float)(vy1_ & vx0_);                       \
            W_[u_][3] = wy1_ * wx1_ * (float)(vy1_ & vx1_);                       \
            I_[u_][0] = y0c_ * WW + x0c_;                                         \
            I_[u_][1] = y0c_ * WW + x1c_;                                         \
            I_[u_][2] = y1c_ * WW + x0c_;                                         \
            I_[u_][3] = y1c_ * WW + x1c_;                                         \
        }                                                                         \
        const float* xb_ = x + ((size_t)(b * CH + dg_ * 64) << 12);               \
        const int krB_ = tid >> 5;                                                \
        const int gn_ = np_ >> 2;                                                 \
        const uint32_t bo_ = (stg_) + ST_B + (np_ & 3) * 4;                       \
        _Pragma("unroll")                                                         \
        for (int j_ = 0; j_ < 8; j_++) {                                          \
            int kr_ = j_ * 8 + krB_;                                              \
            const float* xc_ = xb_ + ((size_t)kr_ << 12);                         \
            float v0_ = W_[0][0]*xc_[I_[0][0]] + W_[0][1]*xc_[I_[0][1]]           \
                      + W_[0][2]*xc_[I_[0][2]] + W_[0][3]*xc_[I_[0][3]];          \
            float v1_ = W_[1][0]*xc_[I_[1][0]] + W_[1][1]*xc_[I_[1][1]]           \
                      + W_[1][2]*xc_[I_[1][2]] + W_[1][3]*xc_[I_[1][3]];          \
            __half2 hv_ = __floats2half2_rn(v0_, v1_);                            \
            uint32_t a_ = bo_ + kr_ * 128 + ((gn_ ^ (kr_ & 7)) << 4);             \
            asm volatile("st.shared.b32 [%0], %1;" :: "r"(a_),                    \
                         "r"(*(uint32_t*)&hv_) : "memory");                       \
        }                                                                         \
        CP_WAIT0();                                                               \
    } while (0)

    // prologue: fill stage 0 with chunk 0
    PRODUCE(0, sb);
    __syncthreads();

    for (int ch = 0; ch < NCHUNK; ch++) {
        const uint32_t buf = sb + (ch & 1) * STAGE;

        // ---- consume chunk ch ----
        #pragma unroll
        for (int kq = 0; kq < 4; kq++) {
            uint32_t aF[2][4], bF[8][2];
            #pragma unroll
            for (int mt = 0; mt < 2; mt++) {
                int r = wid * 32 + mt * 16 + arow;
                uint32_t ad = buf + r * 128 + (((kq * 2 + asel) ^ (r & 7)) << 4);
                LDSM_X4(aF[mt], ad);
            }
            {
                int kr = kq * 16 + bk;
                #pragma unroll
                for (int i = 0; i < 4; i++) {
                    int ng = 2 * i + bsel;
                    uint32_t bd = buf + ST_B + kr * 128 + ((ng ^ (kr & 7)) << 4);
                    LDSM_X4T(bF[2*i][0], bF[2*i][1], bF[2*i+1][0], bF[2*i+1][1], bd);
                }
            }
            #pragma unroll
            for (int mt = 0; mt < 2; mt++)
                #pragma unroll
                for (int nt = 0; nt < 8; nt++) MMA(acc[mt][nt], aF[mt], bF[nt]);
        }

        // ---- produce chunk ch+1 into the other stage ----
        if (ch + 1 < NCHUNK) {
            const uint32_t nbuf = sb + ((ch + 1) & 1) * STAGE;
            PRODUCE(ch + 1, nbuf);
        }
        __syncthreads();
    }

    // ---- epilogue: stores + fused GroupNorm partial stats ----
    #pragma unroll
    for (int mt = 0; mt < 2; mt++) {
        int base = wid * 32 + mt * 16;
        int o = base + (lane >> 2);
        float* r0 = out + ((size_t)(b * CH + o) << 12) + hwB;
        float* r1 = r0 + ((size_t)8 << 12);
        float s0 = 0.f, q0 = 0.f, s1 = 0.f, q1 = 0.f;
        #pragma unroll
        for (int nt = 0; nt < 8; nt++) {
            int c = nt * 8 + (lane & 3) * 2;
            *(float2*)(r0 + c) = make_float2(acc[mt][nt][0], acc[mt][nt][1]);
            *(float2*)(r1 + c) = make_float2(acc[mt][nt][2], acc[mt][nt][3]);
            s0 += acc[mt][nt][0] + acc[mt][nt][1];
            q0 += acc[mt][nt][0] * acc[mt][nt][0] + acc[mt][nt][1] * acc[mt][nt][1];
            s1 += acc[mt][nt][2] + acc[mt][nt][3];
            q1 += acc[mt][nt][2] * acc[mt][nt][2] + acc[mt][nt][3] * acc[mt][nt][3];
        }
        #pragma unroll
        for (int off = 16; off > 0; off >>= 1) {
            s0 += __shfl_xor_sync(0xFFFFFFFFu, s0, off);
            q0 += __shfl_xor_sync(0xFFFFFFFFu, q0, off);
            s1 += __shfl_xor_sync(0xFFFFFFFFu, s1, off);
            q1 += __shfl_xor_sync(0xFFFFFFFFu, q1, off);
        }
        if (lane == 0) {
            int g0 = b * GROUPS + (base >> 3);
            atomicAdd(&g_sum[g0],     s0);
            atomicAdd(&g_sqs[g0],     q0);
            atomicAdd(&g_sum[g0 + 1], s1);
            atomicAdd(&g_sqs[g0 + 1], q1);
        }
    }
}

// ---------------------------------------------------------------------------
// 3) Normalize + affine + ReLU
// ---------------------------------------------------------------------------
__global__ void norm_relu_kernel(float* __restrict__ out,
                                 const float* __restrict__ gamma,
                                 const float* __restrict__ beta) {
    int t  = blockIdx.x * 256 + threadIdx.x;
    int i4 = t * 4;
    int b  = i4 >> 20;
    int c  = (i4 >> 12) & 255;
    int grp = b * GROUPS + (c >> 3);
    float m   = g_sum[grp] * (1.0f / GRP_ELEMS);
    float var = g_sqs[grp] * (1.0f / GRP_ELEMS) - m * m;
    float inv = rsqrtf(var + 1e-5f);
    float ga  = gamma[c] * inv;
    float be  = beta[c] - m * ga;
    float4 v = *(float4*)(out + i4);
    v.x = fmaxf(v.x * ga + be, 0.0f);
    v.y = fmaxf(v.y * ga + be, 0.0f);
    v.z = fmaxf(v.z * ga + be, 0.0f);
    v.w = fmaxf(v.w * ga + be, 0.0f);
    *(float4*)(out + i4) = v;
}

// ---------------------------------------------------------------------------
extern "C" void kernel_launch(void* const* d_in, const int* in_sizes, int n_in,
                              void* d_out, int out_size) {
    const float* x      = (const float*)d_in[0];
    const float* shp    = (const float*)d_in[1];
    const float* w_off  = (const float*)d_in[2];
    const float* w_def  = (const float*)d_in[3];
    const float* gamma  = (const float*)d_in[4];
    const float* beta   = (const float*)d_in[5];
    float* out = (float*)d_out;

    cudaFuncSetAttribute(fused_gemm_kernel,
                         cudaFuncAttributeMaxDynamicSharedMemorySize, GEMM_SMEM);

    repack_kernel<<<2304, 256>>>(w_def);
    fused_gemm_kernel<<<256, 256, GEMM_SMEM>>>(out, x, shp, w_off);
    norm_relu_kernel<<<4096, 256>>>(out, gamma, beta);
}

// round 17
// speedup vs baseline: 1.0043x; 1.0043x over previous
#include <cuda_runtime.h>
#include <cuda_fp16.h>
#include <cstdint>

// Problem constants (fixed shapes)
#define BATCH 4
#define CH    256
#define HH    64
#define WW    64
#define HWSZ  4096
#define KKN   9
#define DGN   4
#define KDIM  2304          // KKN*CH (GEMM K), ordered k' = kk*256 + c
#define NDIM  16384         // BATCH*HWSZ (GEMM N)
#define GROUPS 32
#define GRP_ELEMS 32768

// ---- scratch (device globals; allocation-free) ----
__device__ __align__(16) __half g_wt[CH * KDIM];   // [o][k'], k' = kk*256 + c
__device__ float g_sum[BATCH * GROUPS];
__device__ float g_sqs[BATCH * GROUPS];

// ---------------------------------------------------------------------------
// PTX helpers — family-agnostic only (compute_103 target: no tcgen05/TMA)
// ---------------------------------------------------------------------------
__device__ __forceinline__ uint32_t smem_u32(const void* p) {
    uint32_t a;
    asm("{ .reg .u64 t; cvta.to.shared.u64 t, %1; cvt.u32.u64 %0, t; }" : "=r"(a) : "l"(p));
    return a;
}
__device__ __forceinline__ void cp16(uint32_t dst, const void* src) {
    asm volatile("cp.async.cg.shared.global [%0], [%1], 16;" :: "r"(dst), "l"(src) : "memory");
}
#define CP_COMMIT() asm volatile("cp.async.commit_group;" ::: "memory")
#define CP_WAIT0()  asm volatile("cp.async.wait_group 0;" ::: "memory")

#define LDSM_X4(r, addr) \
    asm volatile("ldmatrix.sync.aligned.m8n8.x4.shared.b16 {%0,%1,%2,%3}, [%4];" \
        : "=r"((r)[0]), "=r"((r)[1]), "=r"((r)[2]), "=r"((r)[3]) : "r"(addr))
#define LDSM_X4T(r0, r1, r2, r3, addr) \
    asm volatile("ldmatrix.sync.aligned.m8n8.x4.trans.shared.b16 {%0,%1,%2,%3}, [%4];" \
        : "=r"(r0), "=r"(r1), "=r"(r2), "=r"(r3) : "r"(addr))

#define MMA(d, a, b) \
    asm volatile("mma.sync.aligned.m16n8k16.row.col.f32.f16.f16.f32 " \
        "{%0,%1,%2,%3}, {%4,%5,%6,%7}, {%8,%9}, {%0,%1,%2,%3};" \
        : "+f"((d)[0]), "+f"((d)[1]), "+f"((d)[2]), "+f"((d)[3]) \
        : "r"((a)[0]), "r"((a)[1]), "r"((a)[2]), "r"((a)[3]), "r"((b)[0]), "r"((b)[1]))

// ---------------------------------------------------------------------------
// 1) Weight repack to fp16, k' = kk*256 + c ordering; zero GN accumulators
//    g_wt[o*2304 + kk*256 + c] = wd[(o*256 + c)*9 + kk]
// ---------------------------------------------------------------------------
__global__ void repack_kernel(const float* __restrict__ wd) {
    int d = blockIdx.x * 256 + threadIdx.x;   // < 589824
    int o  = d / KDIM;
    int r  = d - o * KDIM;
    int kk = r >> 8;
    int c  = r & 255;
    g_wt[d] = __float2half_rn(wd[(o * CH + c) * KKN + kk]);
    if (blockIdx.x == 0 && threadIdx.x < BATCH * GROUPS) {
        g_sum[threadIdx.x] = 0.0f;
        g_sqs[threadIdx.x] = 0.0f;
    }
}

// ---------------------------------------------------------------------------
// 2) FUSED deformable-im2col + fp16 HMMA GEMM + GN partial stats.
//    CTA: M=256 (all o) x N=64 (hw). grid = 256 CTAs (b*64 + hw-tile).
//    K-chunk 64 = chunk ch -> (kk = ch>>2, dg = ch&3); 2-stage smem pipeline.
//    Producer: gather/interp B tile on the fly (col never hits DRAM).
// ---------------------------------------------------------------------------
#define NCHUNK  36
#define ST_B    32768               // A: 256 rows * 128B (XOR swizzle); B: 64 rows * 128B
#define STAGE   40960
#define GEMM_SMEM (2 * STAGE)       // 81920 -> 2 CTAs/SM

__global__ __launch_bounds__(256, 2)
void fused_gemm_kernel(float* __restrict__ out,
                       const float* __restrict__ x,
                       const float* __restrict__ shp,
                       const float* __restrict__ w_off) {
    extern __shared__ __align__(128) char smem[];
    const uint32_t sb = smem_u32(smem);
    const int tid  = threadIdx.x;
    const int lane = tid & 31;
    const int wid  = tid >> 5;
    const int b    = blockIdx.x >> 6;
    const int hwB  = (blockIdx.x & 63) * 64;

    float acc[2][8][4];
    #pragma unroll
    for (int mt = 0; mt < 2; mt++)
        #pragma unroll
        for (int nt = 0; nt < 8; nt++)
            #pragma unroll
            for (int q = 0; q < 4; q++) acc[mt][nt][q] = 0.0f;

    // ldmatrix lane geometry
    const int arow = (lane & 7) + ((lane >> 3) & 1) * 8;
    const int asel = lane >> 4;
    const int bk   = lane & 15;
    const int bsel = lane >> 4;

    // ---- producer: fill stage s with chunk ch ----
    #define PRODUCE(ch_, stg_)                                                    \
    do {                                                                          \
        const int kk_ = (ch_) >> 2, dg_ = (ch_) & 3;                              \
        /* A slab: g_wt[o][ch*64 + g*8], 2048 x 16B, XOR-swizzled rows */         \
        _Pragma("unroll")                                                         \
        for (int p_ = 0; p_ < 8; p_++) {                                          \
            int i_ = tid + p_ * 256;                                              \
            int o_ = i_ >> 3, gg_ = i_ & 7;                                       \
            cp16((stg_) + o_ * 128 + ((gg_ ^ (o_ & 7)) << 4),                     \
                 g_wt + (size_t)o_ * KDIM + (ch_) * 64 + gg_ * 8);                \
        }                                                                         \
        CP_COMMIT();                                                              \
        /* B tile: 64 k-rows x 64 n, each thread: fixed n-pair, 8 k-rows */       \
        const int np_ = tid & 31;                                                 \
        float W_[2][4]; int I_[2][4];                                             \
        _Pragma("unroll")                                                         \
        for (int u_ = 0; u_ < 2; u_++) {                                          \
            int hw_ = hwB + np_ * 2 + u_;                                         \
            int h_ = hw_ >> 6, w_ = hw_ & 63;                                     \
            float s0_ = shp[((b * 4 + 0) << 12) + hw_];                           \
            float s1_ = shp[((b * 4 + 1) << 12) + hw_];                           \
            float s2_ = shp[((b * 4 + 2) << 12) + hw_];                           \
            float s3_ = shp[((b * 4 + 3) << 12) + hw_];                           \
            const float* wo_ = w_off + (dg_ * 18 + kk_ * 2) * 4;                  \
            float dy_ = __ldg(wo_+0)*s0_ + __ldg(wo_+1)*s1_                       \
                      + __ldg(wo_+2)*s2_ + __ldg(wo_+3)*s3_;                      \
            float dx_ = __ldg(wo_+4)*s0_ + __ldg(wo_+5)*s1_                       \
                      + __ldg(wo_+6)*s2_ + __ldg(wo_+7)*s3_;                      \
            float yf_ = (float)(h_ - 1 + kk_ / 3) + dy_;                          \
            float xf_ = (float)(w_ - 1 + kk_ % 3) + dx_;                          \
            float y0f_ = floorf(yf_), x0f_ = floorf(xf_);                         \
            float wy1_ = yf_ - y0f_, wx1_ = xf_ - x0f_;                           \
            float wy0_ = 1.0f - wy1_, wx0_ = 1.0f - wx1_;                         \
            int y0_ = (int)y0f_, x0_ = (int)x0f_;                                 \
            int y1_ = y0_ + 1,   x1_ = x0_ + 1;                                   \
            bool vy0_ = (y0_ >= 0) & (y0_ < HH);                                  \
            bool vy1_ = (y1_ >= 0) & (y1_ < HH);                                  \
            bool vx0_ = (x0_ >= 0) & (x0_ < WW);                                  \
            bool vx1_ = (x1_ >= 0) & (x1_ < WW);                                  \
            int y0c_ = min(max(y0_, 0), HH-1), y1c_ = min(max(y1_, 0), HH-1);     \
            int x0c_ = min(max(x0_, 0), WW-1), x1c_ = min(max(x1_, 0), WW-1);     \
            W_[u_][0] = wy0_ * wx0_ * (float)(vy0_ & vx0_);                       \
            W_[u_][1] = wy0_ * wx1_ * (float)(vy0_ & vx1_);                       \
            W_[u_][2] = wy1_ * wx0_ * (float)(vy1_ & vx0_);                       \
            W_[u_][3] = wy1_ * wx1_ * (float)(vy1_ & vx1_);                       \
            I_[u_][0] = y0c_ * WW + x0c_;                                         \
            I_[u_][1] = y0c_ * WW + x1c_;                                         \
            I_[u_][2] = y1c_ * WW + x0c_;                                         \
            I_[u_][3] = y1c_ * WW + x1c_;                                         \
        }                                                                         \
        const float* xb_ = x + ((size_t)(b * CH + dg_ * 64) << 12);               \
        const int krB_ = tid >> 5;                                                \
        const int gn_ = np_ >> 2;                                                 \
        const uint32_t bo_ = (stg_) + ST_B + (np_ & 3) * 4;                       \
        _Pragma("unroll")                                                         \
        for (int j_ = 0; j_ < 8; j_++) {                                          \
            int kr_ = j_ * 8 + krB_;                                              \
            const float* xc_ = xb_ + ((size_t)kr_ << 12);                         \
            float v0_ = W_[0][0]*xc_[I_[0][0]] + W_[0][1]*xc_[I_[0][1]]           \
                      + W_[0][2]*xc_[I_[0][2]] + W_[0][3]*xc_[I_[0][3]];          \
            float v1_ = W_[1][0]*xc_[I_[1][0]] + W_[1][1]*xc_[I_[1][1]]           \
                      + W_[1][2]*xc_[I_[1][2]] + W_[1][3]*xc_[I_[1][3]];          \
            __half2 hv_ = __floats2half2_rn(v0_, v1_);                            \
            uint32_t a_ = bo_ + kr_ * 128 + ((gn_ ^ (kr_ & 7)) << 4);             \
            asm volatile("st.shared.b32 [%0], %1;" :: "r"(a_),                    \
                         "r"(*(uint32_t*)&hv_) : "memory");                       \
        }                                                                         \
        CP_WAIT0();                                                               \
    } while (0)

    // prologue: fill stage 0 with chunk 0
    PRODUCE(0, sb);
    __syncthreads();

    for (int ch = 0; ch < NCHUNK; ch++) {
        const uint32_t buf = sb + (ch & 1) * STAGE;

        // ---- consume chunk ch ----
        #pragma unroll
        for (int kq = 0; kq < 4; kq++) {
            uint32_t aF[2][4], bF[8][2];
            #pragma unroll
            for (int mt = 0; mt < 2; mt++) {
                int r = wid * 32 + mt * 16 + arow;
                uint32_t ad = buf + r * 128 + (((kq * 2 + asel) ^ (r & 7)) << 4);
                LDSM_X4(aF[mt], ad);
            }
            {
                int kr = kq * 16 + bk;
                #pragma unroll
                for (int i = 0; i < 4; i++) {
                    int ng = 2 * i + bsel;
                    uint32_t bd = buf + ST_B + kr * 128 + ((ng ^ (kr & 7)) << 4);
                    LDSM_X4T(bF[2*i][0], bF[2*i][1], bF[2*i+1][0], bF[2*i+1][1], bd);
                }
            }
            #pragma unroll
            for (int mt = 0; mt < 2; mt++)
                #pragma unroll
                for (int nt = 0; nt < 8; nt++) MMA(acc[mt][nt], aF[mt], bF[nt]);
        }

        // ---- produce chunk ch+1 into the other stage ----
        if (ch + 1 < NCHUNK) {
            const uint32_t nbuf = sb + ((ch + 1) & 1) * STAGE;
            PRODUCE(ch + 1, nbuf);
        }
        __syncthreads();
    }

    // ---- epilogue: stores + fused GroupNorm partial stats ----
    #pragma unroll
    for (int mt = 0; mt < 2; mt++) {
        int base = wid * 32 + mt * 16;
        int o = base + (lane >> 2);
        float* r0 = out + ((size_t)(b * CH + o) << 12) + hwB;
        float* r1 = r0 + ((size_t)8 << 12);
        float s0 = 0.f, q0 = 0.f, s1 = 0.f, q1 = 0.f;
        #pragma unroll
        for (int nt = 0; nt < 8; nt++) {
            int c = nt * 8 + (lane & 3) * 2;
            *(float2*)(r0 + c) = make_float2(acc[mt][nt][0], acc[mt][nt][1]);
            *(float2*)(r1 + c) = make_float2(acc[mt][nt][2], acc[mt][nt][3]);
            s0 += acc[mt][nt][0] + acc[mt][nt][1];
            q0 += acc[mt][nt][0] * acc[mt][nt][0] + acc[mt][nt][1] * acc[mt][nt][1];
            s1 += acc[mt][nt][2] + acc[mt][nt][3];
            q1 += acc[mt][nt][2] * acc[mt][nt][2] + acc[mt][nt][3] * acc[mt][nt][3];
        }
        #pragma unroll
        for (int off = 16; off > 0; off >>= 1) {
            s0 += __shfl_xor_sync(0xFFFFFFFFu, s0, off);
            q0 += __shfl_xor_sync(0xFFFFFFFFu, q0, off);
            s1 += __shfl_xor_sync(0xFFFFFFFFu, s1, off);
            q1 += __shfl_xor_sync(0xFFFFFFFFu, q1, off);
        }
        if (lane == 0) {
            int g0 = b * GROUPS + (base >> 3);
            atomicAdd(&g_sum[g0],     s0);
            atomicAdd(&g_sqs[g0],     q0);
            atomicAdd(&g_sum[g0 + 1], s1);
            atomicAdd(&g_sqs[g0 + 1], q1);
        }
    }
}

// ---------------------------------------------------------------------------
// 3) Normalize + affine + ReLU
// ---------------------------------------------------------------------------
__global__ void norm_relu_kernel(float* __restrict__ out,
                                 const float* __restrict__ gamma,
                                 const float* __restrict__ beta) {
    int t  = blockIdx.x * 256 + threadIdx.x;
    int i4 = t * 4;
    int b  = i4 >> 20;
    int c  = (i4 >> 12) & 255;
    int grp = b * GROUPS + (c >> 3);
    float m   = g_sum[grp] * (1.0f / GRP_ELEMS);
    float var = g_sqs[grp] * (1.0f / GRP_ELEMS) - m * m;
    float inv = rsqrtf(var + 1e-5f);
    float ga  = gamma[c] * inv;
    float be  = beta[c] - m * ga;
    float4 v = *(float4*)(out + i4);
    v.x = fmaxf(v.x * ga + be, 0.0f);
    v.y = fmaxf(v.y * ga + be, 0.0f);
    v.z = fmaxf(v.z * ga + be, 0.0f);
    v.w = fmaxf(v.w * ga + be, 0.0f);
    *(float4*)(out + i4) = v;
}

// ---------------------------------------------------------------------------
extern "C" void kernel_launch(void* const* d_in, const int* in_sizes, int n_in,
                              void* d_out, int out_size) {
    const float* x      = (const float*)d_in[0];
    const float* shp    = (const float*)d_in[1];
    const float* w_off  = (const float*)d_in[2];
    const float* w_def  = (const float*)d_in[3];
    const float* gamma  = (const float*)d_in[4];
    const float* beta   = (const float*)d_in[5];
    float* out = (float*)d_out;

    cudaFuncSetAttribute(fused_gemm_kernel,
                         cudaFuncAttributeMaxDynamicSharedMemorySize, GEMM_SMEM);

    repack_kernel<<<2304, 256>>>(w_def);
    fused_gemm_kernel<<<256, 256, GEMM_SMEM>>>(out, x, shp, w_off);
    norm_relu_kernel<<<4096, 256>>>(out, gamma, beta);
}